// round 17
// baseline (speedup 1.0000x reference)
#include <cuda_runtime.h>
#include <cstdint>

#define SEQ      512
#define BATCH    256
#define INSZ     64
#define HID      256
#define KTOT     320            // reordered contraction: [x 64 | local h 128 | peer h 128]
#define G        4
#define NTHREADS 512            // 16 warps: kw = w&7, jh = w>>3
#define KSPLIT   8
#define C2W      10             // ulonglong2 chunks per 40-float A-warp K-range

#define STAGE_FLOATS (128 * KTOT)            // 40960 staging; dead after init -> red buffers
#define RHS_FLOATS   (2 * G * KTOT)          // 2560 double-buffered rows
#define RED_U64      (KSPLIT * G * 128)      // 4096 u64 per red buffer (2 buffers in staging)
#define SMEM_BYTES   ((STAGE_FLOATS + RHS_FLOATS + 128) * 4 + 4 * 8)

#define K_X      0
#define K_LOC    64
#define K_PEER   192

__device__ __forceinline__ void fma2(unsigned long long& d, unsigned long long a, unsigned long long b) {
    asm("fma.rn.f32x2 %0, %1, %2, %0;" : "+l"(d) : "l"(a), "l"(b));
}
__device__ __forceinline__ void add2(unsigned long long& d, unsigned long long a) {
    asm("add.rn.f32x2 %0, %0, %1;" : "+l"(d) : "l"(a));
}
__device__ __forceinline__ void mbar_wait(unsigned addr, int phase) {
    asm volatile(
        "{\n\t.reg .pred P;\n\t"
        "WAITL%=:\n\t"
        "mbarrier.try_wait.parity.acquire.cta.shared::cta.b64 P, [%0], %1, 0x989680;\n\t"
        "@P bra DONE%=;\n\t"
        "bra WAITL%=;\n\t"
        "DONE%=:\n\t}"
        :: "r"(addr), "r"(phase) : "memory");
}

__global__ void __cluster_dims__(2, 1, 1) __launch_bounds__(NTHREADS, 1)
rnn_persistent_kernel(const float* __restrict__ x,  const float* __restrict__ Wx,
                      const float* __restrict__ bx, const float* __restrict__ Wh,
                      const float* __restrict__ bh, float* __restrict__ out)
{
    extern __shared__ float sm[];
    float* wh_s  = sm;                                    // staging (init only) -> red bufs
    float* rhs_s = sm + STAGE_FLOATS;                     // [2][G][320]
    float* bsum_s = rhs_s + RHS_FLOATS;                   // [128]
    unsigned long long* mbar = (unsigned long long*)(bsum_s + 128);  // [self0,peer0,self1,peer1]

    const int tid   = threadIdx.x;
    const int rank  = blockIdx.x & 1;
    const int b0    = (blockIdx.x >> 1) * G;
    const int jbase = rank * 128;
    const int pbase = 128 - jbase;
    const int w     = tid >> 5;
    const int l     = tid & 31;
    const int kw    = w & (KSPLIT - 1);
    const int jh    = w >> 3;
    const bool isB  = (kw >= 4);
    const int bw    = kw - 4;

    // ---- init: stage weights in reordered K layout ----
    for (int idx = tid; idx < 128 * KTOT; idx += NTHREADS) {
        int j = idx / KTOT;
        int k = idx - j * KTOT;
        int jg = jbase + j;
        float v;
        if (k < K_LOC)        v = Wx[jg * INSZ + k];
        else if (k < K_PEER)  v = Wh[jg * HID + jbase + (k - K_LOC)];
        else                  v = Wh[jg * HID + pbase + (k - K_PEER)];
        wh_s[idx] = v;
    }
    if (tid < 128) bsum_s[tid] = bh[jbase + tid] + bx[jbase + tid];
    for (int idx = tid; idx < G * KTOT; idx += NTHREADS) {
        int b = idx / KTOT;
        int k = idx - b * KTOT;
        rhs_s[idx] = (k < K_LOC) ? x[(size_t)(b0 + b) * INSZ + k] : 0.f;
    }
    unsigned mb_s0 = (unsigned)__cvta_generic_to_shared(mbar);
    if (tid == 0) {
        #pragma unroll
        for (int i = 0; i < 4; ++i)
            asm volatile("mbarrier.init.shared.b64 [%0], 1;" :: "r"(mb_s0 + 8u * i) : "memory");
    }
    __syncthreads();

    // ---- weights -> registers (R14 asymmetric layout) ----
    // A-warp (kw<4): K chunk [40kw, 40kw+40)
    // B-warp: 8 local floats [160+8bw, +8) then 32 peer floats [192+32bw, +32)
    unsigned long long wreg[2][2 * C2W];   // 20 u64 per j-row
    #pragma unroll
    for (int jj = 0; jj < 2; ++jj) {
        const float* rowp = wh_s + (jh * 64 + l + 32 * jj) * KTOT;
        if (!isB) {
            const unsigned long long* wr = (const unsigned long long*)(rowp + 40 * kw);
            #pragma unroll
            for (int p = 0; p < 20; ++p) wreg[jj][p] = wr[p];
        } else {
            const unsigned long long* wl = (const unsigned long long*)(rowp + 160 + 8 * bw);
            #pragma unroll
            for (int p = 0; p < 4; ++p) wreg[jj][p] = wl[p];
            const unsigned long long* wp = (const unsigned long long*)(rowp + K_PEER + 32 * bw);
            #pragma unroll
            for (int p = 0; p < 16; ++p) wreg[jj][4 + p] = wp[p];
        }
    }
    asm volatile("barrier.cluster.arrive.aligned;" ::: "memory");
    asm volatile("barrier.cluster.wait.aligned;"   ::: "memory");

    const int jr = tid & 127;       // epilogue: local j
    const int br = tid >> 7;        // epilogue: batch index
    const int bb = tid >> 6;        // x prefetch batch lane (tid<256)
    const int xi = tid & 63;
    int ph0 = 0, ph1 = 0;           // one phase per buffer (self & peer flip together)

    float* outt     = out;
    float* out_last = out + (size_t)SEQ * BATCH * HID;

    for (int t = 0; t < SEQ; ++t) {
        const int cur = t & 1;
        const int nxt = cur ^ 1;
        const unsigned mb_self_cur = mb_s0 + cur * 16;
        const unsigned mb_peer_cur = mb_self_cur + 8;
        const unsigned mb_self_nxt = mb_s0 + nxt * 16;
        const unsigned mb_peer_nxt = mb_self_nxt + 8;

        // post expectations for NEXT buffer (self: 2KB h + 1KB x; peer: 2KB h)
        if (tid == 0 && t + 1 < SEQ) {
            asm volatile("mbarrier.arrive.expect_tx.shared.b64 _, [%0], %1;"
                         :: "r"(mb_self_nxt), "r"(3072u) : "memory");
            asm volatile("mbarrier.arrive.expect_tx.shared.b64 _, [%0], %1;"
                         :: "r"(mb_peer_nxt), "r"(2048u) : "memory");
        }

        // prefetch next timestep's x
        float xv = 0.f;
        if (t + 1 < SEQ && tid < G * INSZ)
            xv = x[(size_t)(t + 1) * BATCH * INSZ + (size_t)(b0 + bb) * INSZ + xi];

        // all warps: wait for own x + local h of this step (replaces bar2)
        if (t > 0) mbar_wait(mb_self_cur, cur ? ph1 : ph0);

        unsigned long long acc[2][4];
        #pragma unroll
        for (int jj = 0; jj < 2; ++jj)
            #pragma unroll
            for (int b = 0; b < 4; ++b) acc[jj][b] = 0ull;

        const float* rbase = rhs_s + cur * (G * KTOT);

        if (!isB) {
            // ---- A GEMM: 10 chunks over [40kw, +40) ----
            const ulonglong2* rc2 = (const ulonglong2*)(rbase + 40 * kw);
            #pragma unroll
            for (int it = 0; it < C2W; ++it) {
                #pragma unroll
                for (int b = 0; b < 4; ++b) {
                    ulonglong2 hv = rc2[b * (KTOT / 4) + it];
                    #pragma unroll
                    for (int jj = 0; jj < 2; ++jj) {
                        fma2(acc[jj][b], wreg[jj][2 * it],     hv.x);
                        fma2(acc[jj][b], wreg[jj][2 * it + 1], hv.y);
                    }
                }
            }
        } else {
            // ---- B GEMM: 2 local chunks first (absorb peer skew) ----
            const ulonglong2* rl = (const ulonglong2*)(rbase + 160 + 8 * bw);
            #pragma unroll
            for (int it = 0; it < 2; ++it) {
                #pragma unroll
                for (int b = 0; b < 4; ++b) {
                    ulonglong2 hv = rl[b * (KTOT / 4) + it];
                    #pragma unroll
                    for (int jj = 0; jj < 2; ++jj) {
                        fma2(acc[jj][b], wreg[jj][2 * it],     hv.x);
                        fma2(acc[jj][b], wreg[jj][2 * it + 1], hv.y);
                    }
                }
            }
            // wait for peer h of step t-1
            if (t > 0) mbar_wait(mb_peer_cur, cur ? ph1 : ph0);
            // ---- 8 peer chunks over [192+32bw, +32) ----
            const ulonglong2* rp = (const ulonglong2*)(rbase + K_PEER + 32 * bw);
            #pragma unroll
            for (int it = 0; it < 8; ++it) {
                #pragma unroll
                for (int b = 0; b < 4; ++b) {
                    ulonglong2 hv = rp[b * (KTOT / 4) + it];
                    #pragma unroll
                    for (int jj = 0; jj < 2; ++jj) {
                        fma2(acc[jj][b], wreg[jj][4 + 2 * it],     hv.x);
                        fma2(acc[jj][b], wreg[jj][4 + 2 * it + 1], hv.y);
                    }
                }
            }
        }
        if (t > 0) { if (cur) ph1 ^= 1; else ph0 ^= 1; }

        // ---- stash partials into DOUBLE-BUFFERED red (in dead staging region) ----
        unsigned long long* red_s = (unsigned long long*)sm + (size_t)cur * RED_U64;
        #pragma unroll
        for (int jj = 0; jj < 2; ++jj) {
            const int j = jh * 64 + l + 32 * jj;
            #pragma unroll
            for (int b = 0; b < 4; ++b)
                red_s[(size_t)(kw * 4 + b) * 128 + j] = acc[jj][b];
        }
        __syncthreads();   // bar1: stash visible to reducers

        // ---- reduce(8) + bias + tanh + exchange + output: ONE output per thread ----
        float* rnext = rhs_s + nxt * (G * KTOT);
        {
            const unsigned long long* q = red_s + (size_t)br * 128 + jr;
            unsigned long long s2 = q[0];
            #pragma unroll
            for (int ww = 1; ww < KSPLIT; ++ww) add2(s2, q[(size_t)ww * 512]);
            float lo, hi;
            asm("mov.b64 {%0, %1}, %2;" : "=f"(lo), "=f"(hi) : "l"(s2));
            float z = lo + hi + bsum_s[jr];
            // tanh(z) = 1 - 2/(exp2(2z*log2e)+1)
            float ex;  asm("ex2.approx.f32 %0, %1;" : "=f"(ex)  : "f"(z * 2.885390081777927f));
            float rcp; asm("rcp.approx.f32 %0, %1;" : "=f"(rcp) : "f"(ex + 1.0f));
            float h = fmaf(-2.0f, rcp, 1.0f);

            if (t + 1 < SEQ) {
                // peer-h: to peer's PEER region, tracked by peer's mb_peer(nxt)
                unsigned lap = (unsigned)__cvta_generic_to_shared(&rnext[br * KTOT + K_PEER + jr]);
                unsigned rap, ramb_p;
                asm("mapa.shared::cluster.u32 %0, %1, %2;" : "=r"(rap)    : "r"(lap),         "r"(rank ^ 1));
                asm("mapa.shared::cluster.u32 %0, %1, %2;" : "=r"(ramb_p) : "r"(mb_peer_nxt), "r"(rank ^ 1));
                asm volatile("st.async.shared::cluster.mbarrier::complete_tx::bytes.b32 [%0], %1, [%2];"
                             :: "r"(rap), "f"(h), "r"(ramb_p) : "memory");
                // self-h: to OUR LOCAL region, tracked by OUR mb_self(nxt)
                unsigned las = (unsigned)__cvta_generic_to_shared(&rnext[br * KTOT + K_LOC + jr]);
                unsigned ras, ramb_s;
                asm("mapa.shared::cluster.u32 %0, %1, %2;" : "=r"(ras)    : "r"(las),         "r"(rank));
                asm("mapa.shared::cluster.u32 %0, %1, %2;" : "=r"(ramb_s) : "r"(mb_self_nxt), "r"(rank));
                asm volatile("st.async.shared::cluster.mbarrier::complete_tx::bytes.b32 [%0], %1, [%2];"
                             :: "r"(ras), "f"(h), "r"(ramb_s) : "memory");
            }

            const int jg = jbase + jr;
            const int bg = b0 + br;
            outt[(size_t)bg * HID + jg] = h;                // coalesced 128B
            if (t == SEQ - 1) out_last[(size_t)bg * HID + jg] = h;
        }
        // x staging also via self st.async (counted in mb_self's 3072B)
        if (t + 1 < SEQ && tid < G * INSZ) {
            unsigned lax = (unsigned)__cvta_generic_to_shared(&rnext[bb * KTOT + K_X + xi]);
            unsigned rax, ramb_s;
            asm("mapa.shared::cluster.u32 %0, %1, %2;" : "=r"(rax)    : "r"(lax),         "r"(rank));
            asm("mapa.shared::cluster.u32 %0, %1, %2;" : "=r"(ramb_s) : "r"(mb_self_nxt), "r"(rank));
            asm volatile("st.async.shared::cluster.mbarrier::complete_tx::bytes.b32 [%0], %1, [%2];"
                         :: "r"(rax), "f"(xv), "r"(ramb_s) : "memory");
        }
        outt += BATCH * HID;
        // NO bar2 — next step gated by mb_self/mb_peer waits
    }
}

extern "C" void kernel_launch(void* const* d_in, const int* in_sizes, int n_in,
                              void* d_out, int out_size) {
    const float* x  = (const float*)d_in[0];
    const float* Wx = (const float*)d_in[1];
    const float* bx = (const float*)d_in[2];
    const float* Wh = (const float*)d_in[3];
    const float* bh = (const float*)d_in[4];
    float* out = (float*)d_out;
    (void)in_sizes; (void)n_in; (void)out_size;

    cudaFuncSetAttribute(rnn_persistent_kernel,
                         cudaFuncAttributeMaxDynamicSharedMemorySize, SMEM_BYTES);
    rnn_persistent_kernel<<<128, NTHREADS, SMEM_BYTES>>>(x, Wx, bx, Wh, bh, out);
}